// round 1
// baseline (speedup 1.0000x reference)
#include <cuda_runtime.h>
#include <math.h>

// LIF_R one step:
//   I        = w @ g + x_in                    (w: [N,N] fp32 row-major, the 256MB hot loop)
//   dv       = (G*(E_L - v) + I*R_I) / C_m
//   v_next   = v + dv
//   s_soft   = sigmoid(v_next - theta_s)
//   spiked   = (v_next >= theta_s) ? 1 : 0
//   v_reset  = E_L + F_V*(v - E_L) - DELTA_V
//   v_new    = spiked ? v_reset : v_next
// out[0:N] = v_new, out[N:2N] = s_soft

#define THREADS 256
#define WARPS_PER_BLOCK 8   // = rows per block

__constant__ float c_R_I     = 18.0f;
__constant__ float c_F_V     = 0.12f;
__constant__ float c_DELTA_V = 12.0f;

__global__ __launch_bounds__(THREADS, 8)
void lif_r_kernel(const float* __restrict__ x_in,
                  const float* __restrict__ v,
                  const float* __restrict__ g,
                  const float* __restrict__ theta_s,
                  const float* __restrict__ w,
                  const float* __restrict__ E_L,
                  const float* __restrict__ C_m,
                  const float* __restrict__ G,
                  const float* __restrict__ tau_g,
                  float* __restrict__ out,
                  int n)
{
    extern __shared__ float sg[];            // n floats (32 KB for N=8192)
    const int tid = threadIdx.x;

    // Stage g into shared memory (vectorized, coalesced).
    const int n4 = n >> 2;
    const float4* __restrict__ g4 = reinterpret_cast<const float4*>(g);
    float4* sg4 = reinterpret_cast<float4*>(sg);
    for (int i = tid; i < n4; i += THREADS) sg4[i] = g4[i];
    __syncthreads();

    const int warp = tid >> 5;
    const int lane = tid & 31;
    const int row  = blockIdx.x * WARPS_PER_BLOCK + warp;
    if (row >= n) return;

    const float4* __restrict__ wrow =
        reinterpret_cast<const float4*>(w + (size_t)row * (size_t)n);

    // Dot product: lanes stride float4s across the row. 64 iters/lane at N=8192.
    float ax = 0.f, ay = 0.f, az = 0.f, aw = 0.f;
    #pragma unroll 8
    for (int c = lane; c < n4; c += 32) {
        float4 wv = wrow[c];
        float4 gv = sg4[c];
        ax = fmaf(wv.x, gv.x, ax);
        ay = fmaf(wv.y, gv.y, ay);
        az = fmaf(wv.z, gv.z, az);
        aw = fmaf(wv.w, gv.w, aw);
    }
    float acc = (ax + ay) + (az + aw);

    // Warp reduction.
    #pragma unroll
    for (int off = 16; off > 0; off >>= 1)
        acc += __shfl_xor_sync(0xffffffffu, acc, off);

    if (lane == 0) {
        const float vi   = v[row];
        const float th   = theta_s[row];
        const float el   = E_L[row];
        const float gi   = G[row];
        const float cm   = C_m[row];

        const float I      = acc + x_in[row];
        const float dv     = (gi * (el - vi) + I * c_R_I) / cm;
        const float v_next = vi + dv;

        // differentiable surrogate
        const float s_soft = 1.0f / (1.0f + __expf(-(v_next - th)));

        const float spiked  = (v_next >= th) ? 1.0f : 0.0f;
        const float v_reset = el + c_F_V * (vi - el) - c_DELTA_V;
        const float v_new   = spiked * v_reset + (1.0f - spiked) * v_next;

        out[row]     = v_new;
        out[n + row] = s_soft;
    }
}

extern "C" void kernel_launch(void* const* d_in, const int* in_sizes, int n_in,
                              void* d_out, int out_size)
{
    // metadata order: x_in, v, g, theta_s, w, E_L, C_m, G, tau_g
    const float* x_in    = (const float*)d_in[0];
    const float* v       = (const float*)d_in[1];
    const float* g       = (const float*)d_in[2];
    const float* theta_s = (const float*)d_in[3];
    const float* w       = (const float*)d_in[4];
    const float* E_L     = (const float*)d_in[5];
    const float* C_m     = (const float*)d_in[6];
    const float* G       = (const float*)d_in[7];
    const float* tau_g   = (const float*)d_in[8];
    float* out = (float*)d_out;

    const int n = in_sizes[0];
    const int blocks = (n + WARPS_PER_BLOCK - 1) / WARPS_PER_BLOCK;
    const size_t smem = (size_t)n * sizeof(float);

    lif_r_kernel<<<blocks, THREADS, smem>>>(x_in, v, g, theta_s, w,
                                            E_L, C_m, G, tau_g, out, n);
}